// round 1
// baseline (speedup 1.0000x reference)
#include <cuda_runtime.h>
#include <math.h>
#include <cstdint>

#define N_FILT  80
#define HALF    126     // folded taps k = 0..125 (k pairs with 250-k; k=125 is center)
#define SEQ     32000
#define BATCH   32
#define TI      256     // output positions per block
#define KC      18      // k-chunk (126 = 7*18)
#define NCHUNK  7
#define THREADS 320

// Folded filters, layout [k][o] for coalesced loads. 126*80 floats.
__device__ float g_filt[HALF * N_FILT];

// ---------------------------------------------------------------------------
// Kernel A: build folded filters. One block per filter, 128 threads.
// Replicates the reference arithmetic order in fp32; sin/cos evaluated in
// double of the fp32-rounded argument (args reach ~6e6; matches libdevice
// __nv_sinf to ~ulp and is immune to --use_fast_math).
// ---------------------------------------------------------------------------
__global__ void gen_filters_kernel(const float* __restrict__ fb1,
                                   const float* __restrict__ fband) {
    const int o = blockIdx.x;
    const int k = threadIdx.x;          // tap index 0..125 (125 = center)
    const float two_pi = 6.2831853071795864769f;
    const float fs = 16000.0f;
    const float minf = 50.0f / fs;
    const float beg = fabsf(fb1[o]) + minf;
    const float end = beg + fabsf(fband[o]) + minf;

    float val = 0.0f;
    float bpv = -3.0e38f;
    if (k < HALF) {
        const int ti = 125 - k;         // t_right value (0 at center)
        if (ti == 0) {
            val = 2.0f * end - 2.0f * beg;
        } else {
            const float t  = (float)ti;
            const float ce = two_pi * (end * fs);
            const float cb = two_pi * (beg * fs);
            const float ae = ce * t;
            const float ab = cb * t;
            const float ye = (float)sin((double)ae) / ae;
            const float yb = (float)sin((double)ab) / ab;
            val = (2.0f * end) * ye - (2.0f * beg) * yb;
        }
        bpv = val;
    }
    // max over the 251-tap row == max over the symmetric 126 half
    __shared__ float red[128];
    red[threadIdx.x] = bpv;
    __syncthreads();
    for (int s = 64; s > 0; s >>= 1) {
        if (threadIdx.x < s)
            red[threadIdx.x] = fmaxf(red[threadIdx.x], red[threadIdx.x + s]);
        __syncthreads();
    }
    const float mx = red[0];
    if (k < HALF) {
        const float nk  = (float)k * (251.0f / 250.0f);   // linspace(0,251,251)[k]
        const float wa  = (two_pi * nk) / 251.0f;
        const float win = 0.54f - 0.46f * (float)cos((double)wa);
        g_filt[k * N_FILT + o] = (val / mx) * win;
    }
}

// ---------------------------------------------------------------------------
// Kernel B: symmetric conv as smem GEMM, 80 filters x 256 positions per block.
// Thread tile: 4 consecutive filters x 16 positions (4 interleaved float4
// chunks -> conflict-free LDS.128). Accumulate in packed fp32x2.
// ---------------------------------------------------------------------------
__global__ void __launch_bounds__(THREADS)
conv_kernel(const float* __restrict__ x, float* __restrict__ out) {
    __shared__ float sF[KC * N_FILT];   // filter chunk [kk][o]      (1440 f)
    __shared__ float sX[512];           // x tile, TI + 250 used     ( 506 f)
    __shared__ float sP[KC * TI];       // pair sums [kk][i]         (4608 f)

    const int tid = threadIdx.x;
    const int b   = blockIdx.y;
    const int J0  = blockIdx.x * TI;
    const float* xb = x + (size_t)b * SEQ;

    // load x segment [J0-125, J0+TI+125) with zero padding
    for (int i = tid; i < TI + 250; i += THREADS) {
        const int g = J0 - 125 + i;
        sX[i] = (g >= 0 && g < SEQ) ? xb[g] : 0.0f;
    }

    const int fg = tid >> 4;    // 0..19 : filter group (4 filters)
    const int ig = tid & 15;    // 0..15 : interleaved position chunk base

    unsigned long long acc[4][8];   // [filter][position pair], fp32x2 each
#pragma unroll
    for (int f = 0; f < 4; ++f)
#pragma unroll
        for (int p = 0; p < 8; ++p) acc[f][p] = 0ULL;

    __syncthreads();

    for (int c = 0; c < NCHUNK; ++c) {
        const int k0 = c * KC;
        // stage filter chunk (coalesced from global; L2-hot after wave 1)
        for (int idx = tid; idx < KC * N_FILT; idx += THREADS)
            sF[idx] = g_filt[k0 * N_FILT + idx];
        // stage pair sums P[kk][i] = x[i+k] + x[i+250-k]  (center: single tap)
        for (int idx = tid; idx < KC * TI; idx += THREADS) {
            const int kk = idx >> 8;            // / TI
            const int i  = idx & (TI - 1);
            const int k  = k0 + kk;
            sP[kk * TI + i] = (k == 125) ? sX[i + 125]
                                         : (sX[i + k] + sX[i + 250 - k]);
        }
        __syncthreads();

#pragma unroll
        for (int kk = 0; kk < KC; ++kk) {
            // 4 filter coefs (warp-broadcast), duplicated into fp32x2
            const float4 f4 =
                *reinterpret_cast<const float4*>(&sF[kk * N_FILT + fg * 4]);
            unsigned long long fd0, fd1, fd2, fd3;
            asm("mov.b64 %0, {%1, %1};" : "=l"(fd0) : "f"(f4.x));
            asm("mov.b64 %0, {%1, %1};" : "=l"(fd1) : "f"(f4.y));
            asm("mov.b64 %0, {%1, %1};" : "=l"(fd2) : "f"(f4.z));
            asm("mov.b64 %0, {%1, %1};" : "=l"(fd3) : "f"(f4.w));
            // 16 positions as 8 packed pairs (4 interleaved float4 chunks)
            unsigned long long pp[8];
#pragma unroll
            for (int j = 0; j < 4; ++j) {
                const ulonglong2 pv = *reinterpret_cast<const ulonglong2*>(
                    &sP[kk * TI + (ig + 16 * j) * 4]);
                pp[2 * j]     = pv.x;
                pp[2 * j + 1] = pv.y;
            }
            // 32 packed FMAs = 64 fp32 FMA lanes
#pragma unroll
            for (int p = 0; p < 8; ++p) {
                asm("fma.rn.f32x2 %0, %1, %2, %0;" : "+l"(acc[0][p]) : "l"(fd0), "l"(pp[p]));
                asm("fma.rn.f32x2 %0, %1, %2, %0;" : "+l"(acc[1][p]) : "l"(fd1), "l"(pp[p]));
                asm("fma.rn.f32x2 %0, %1, %2, %0;" : "+l"(acc[2][p]) : "l"(fd2), "l"(pp[p]));
                asm("fma.rn.f32x2 %0, %1, %2, %0;" : "+l"(acc[3][p]) : "l"(fd3), "l"(pp[p]));
            }
        }
        __syncthreads();
    }

    // epilogue: unpack and store (float4, coalesced in 16B-interleaved chunks)
#pragma unroll
    for (int f = 0; f < 4; ++f) {
        const int o = fg * 4 + f;
        float* op = out + (size_t)(b * N_FILT + o) * SEQ + J0;
#pragma unroll
        for (int j = 0; j < 4; ++j) {
            float4 v;
            asm("mov.b64 {%0, %1}, %2;" : "=f"(v.x), "=f"(v.y) : "l"(acc[f][2 * j]));
            asm("mov.b64 {%0, %1}, %2;" : "=f"(v.z), "=f"(v.w) : "l"(acc[f][2 * j + 1]));
            *reinterpret_cast<float4*>(op + (ig + 16 * j) * 4) = v;
        }
    }
}

// ---------------------------------------------------------------------------
extern "C" void kernel_launch(void* const* d_in, const int* in_sizes, int n_in,
                              void* d_out, int out_size) {
    const float* x     = (const float*)d_in[0];
    const float* fb1   = (const float*)d_in[1];
    const float* fband = (const float*)d_in[2];
    float* out = (float*)d_out;

    gen_filters_kernel<<<N_FILT, 128>>>(fb1, fband);
    conv_kernel<<<dim3(SEQ / TI, BATCH), THREADS>>>(x, out);
}

// round 2
// speedup vs baseline: 1.2137x; 1.2137x over previous
#include <cuda_runtime.h>
#include <math.h>
#include <cstdint>

#define N_FILT  80
#define HALF    126     // folded taps k = 0..125 (k pairs with 250-k; k=125 is center)
#define SEQ     32000
#define BATCH   32
#define TI      256     // output positions per block
#define KC      18      // k-chunk (126 = 7*18)
#define NCHUNK  7
#define THREADS 320

// Folded filters, pre-duplicated into f32x2 lanes: g_filt[k][o] = (f, f).
// Center tap (k=125) stored pre-halved so the conv pair-sum is uniform.
__device__ float2 g_filt[HALF * N_FILT];

// ---------------------------------------------------------------------------
// Kernel A: build folded filters. One block per filter, 128 threads.
// sin/cos evaluated in double of the fp32-rounded argument (args reach ~6e6;
// matches libdevice __nv_sinf to ~ulp and is immune to --use_fast_math).
// ---------------------------------------------------------------------------
__global__ void gen_filters_kernel(const float* __restrict__ fb1,
                                   const float* __restrict__ fband) {
    const int o = blockIdx.x;
    const int k = threadIdx.x;          // tap index 0..125 (125 = center)
    const float two_pi = 6.2831853071795864769f;
    const float fs = 16000.0f;
    const float minf = 50.0f / fs;
    const float beg = fabsf(fb1[o]) + minf;
    const float end = beg + fabsf(fband[o]) + minf;

    float val = 0.0f;
    float bpv = -3.0e38f;
    if (k < HALF) {
        const int ti = 125 - k;         // t_right value (0 at center)
        if (ti == 0) {
            val = 2.0f * end - 2.0f * beg;
        } else {
            const float t  = (float)ti;
            const float ce = two_pi * (end * fs);
            const float cb = two_pi * (beg * fs);
            const float ae = ce * t;
            const float ab = cb * t;
            const float ye = (float)sin((double)ae) / ae;
            const float yb = (float)sin((double)ab) / ab;
            val = (2.0f * end) * ye - (2.0f * beg) * yb;
        }
        bpv = val;
    }
    // max over the 251-tap row == max over the symmetric 126 half
    __shared__ float red[128];
    red[threadIdx.x] = bpv;
    __syncthreads();
    for (int s = 64; s > 0; s >>= 1) {
        if (threadIdx.x < s)
            red[threadIdx.x] = fmaxf(red[threadIdx.x], red[threadIdx.x + s]);
        __syncthreads();
    }
    const float mx = red[0];
    if (k < HALF) {
        const float nk  = (float)k * (251.0f / 250.0f);   // linspace(0,251,251)[k]
        const float wa  = (two_pi * nk) / 251.0f;
        const float win = 0.54f - 0.46f * (float)cos((double)wa);
        float fv = (val / mx) * win;
        if (k == 125) fv *= 0.5f;       // center: conv pair-sum doubles it back
        g_filt[k * N_FILT + o] = make_float2(fv, fv);
    }
}

// ---------------------------------------------------------------------------
// Kernel B: symmetric conv as smem GEMM, 80 filters x 256 positions per block.
// Thread tile: 4 consecutive filters x 16 positions (4 interleaved float4
// chunks -> conflict-free LDS.128). Accumulate in packed fp32x2.
// 2 CTAs/SM: one CTA's FFMA2 stream covers the other's build/barrier phase.
// ---------------------------------------------------------------------------
__global__ void __launch_bounds__(THREADS, 2)
conv_kernel(const float* __restrict__ x, float* __restrict__ out) {
    __shared__ float2 sFd[KC * N_FILT]; // duplicated filter chunk (11520 B)
    __shared__ float  sX[512];          // x tile, TI + 250 used     (2048 B)
    __shared__ float  sP[KC * TI];      // pair sums [kk][i]        (18432 B)

    const int tid = threadIdx.x;
    const int b   = blockIdx.y;
    const int J0  = blockIdx.x * TI;
    const float* xb = x + (size_t)b * SEQ;

    // load x segment [J0-125, J0+TI+125) with zero padding
    for (int i = tid; i < TI + 250; i += THREADS) {
        const int g = J0 - 125 + i;
        sX[i] = (g >= 0 && g < SEQ) ? xb[g] : 0.0f;
    }

    const int fg = tid >> 4;    // 0..19 : filter group (4 filters)
    const int ig = tid & 15;    // 0..15 : interleaved position chunk base

    unsigned long long acc[4][8];   // [filter][position pair], fp32x2 each
#pragma unroll
    for (int f = 0; f < 4; ++f)
#pragma unroll
        for (int p = 0; p < 8; ++p) acc[f][p] = 0ULL;

    __syncthreads();

    for (int c = 0; c < NCHUNK; ++c) {
        const int k0 = c * KC;
        // stage duplicated filter chunk (L2-hot after wave 1)
        for (int idx = tid; idx < KC * N_FILT; idx += THREADS)
            sFd[idx] = g_filt[k0 * N_FILT + idx];
        // stage pair sums P[kk][i] = x[i+k] + x[i+250-k]  (uniform, center pre-halved)
        for (int idx = tid; idx < KC * TI; idx += THREADS) {
            const int kk = idx >> 8;            // / TI
            const int i  = idx & (TI - 1);
            const int k  = k0 + kk;
            sP[kk * TI + i] = sX[i + k] + sX[i + 250 - k];
        }
        __syncthreads();

#pragma unroll
        for (int kk = 0; kk < KC; ++kk) {
            // 4 duplicated filter coefs: 2 broadcast LDS.128
            const ulonglong2 fa =
                *reinterpret_cast<const ulonglong2*>(&sFd[kk * N_FILT + fg * 4]);
            const ulonglong2 fb =
                *reinterpret_cast<const ulonglong2*>(&sFd[kk * N_FILT + fg * 4 + 2]);
            // 16 positions as 8 packed pairs (4 interleaved float4 chunks)
            unsigned long long pp[8];
#pragma unroll
            for (int j = 0; j < 4; ++j) {
                const ulonglong2 pv = *reinterpret_cast<const ulonglong2*>(
                    &sP[kk * TI + (ig + 16 * j) * 4]);
                pp[2 * j]     = pv.x;
                pp[2 * j + 1] = pv.y;
            }
            // 32 packed FMAs = 64 fp32 FMA lanes
#pragma unroll
            for (int p = 0; p < 8; ++p) {
                asm("fma.rn.f32x2 %0, %1, %2, %0;" : "+l"(acc[0][p]) : "l"(fa.x), "l"(pp[p]));
                asm("fma.rn.f32x2 %0, %1, %2, %0;" : "+l"(acc[1][p]) : "l"(fa.y), "l"(pp[p]));
                asm("fma.rn.f32x2 %0, %1, %2, %0;" : "+l"(acc[2][p]) : "l"(fb.x), "l"(pp[p]));
                asm("fma.rn.f32x2 %0, %1, %2, %0;" : "+l"(acc[3][p]) : "l"(fb.y), "l"(pp[p]));
            }
        }
        __syncthreads();
    }

    // epilogue: unpack and store (float4, coalesced in 16B-interleaved chunks)
#pragma unroll
    for (int f = 0; f < 4; ++f) {
        const int o = fg * 4 + f;
        float* op = out + (size_t)(b * N_FILT + o) * SEQ + J0;
#pragma unroll
        for (int j = 0; j < 4; ++j) {
            float4 v;
            asm("mov.b64 {%0, %1}, %2;" : "=f"(v.x), "=f"(v.y) : "l"(acc[f][2 * j]));
            asm("mov.b64 {%0, %1}, %2;" : "=f"(v.z), "=f"(v.w) : "l"(acc[f][2 * j + 1]));
            *reinterpret_cast<float4*>(op + (ig + 16 * j) * 4) = v;
        }
    }
}

// ---------------------------------------------------------------------------
extern "C" void kernel_launch(void* const* d_in, const int* in_sizes, int n_in,
                              void* d_out, int out_size) {
    const float* x     = (const float*)d_in[0];
    const float* fb1   = (const float*)d_in[1];
    const float* fband = (const float*)d_in[2];
    float* out = (float*)d_out;

    gen_filters_kernel<<<N_FILT, 128>>>(fb1, fband);
    conv_kernel<<<dim3(SEQ / TI, BATCH), THREADS>>>(x, out);
}